// round 11
// baseline (speedup 1.0000x reference)
#include <cuda_runtime.h>
#include <cstdint>

constexpr int C_   = 192;
constexpr int H_   = 192;
constexpr int W_   = 192;
constexpr int SS_  = 4;
constexpr int NWIN = 8 * 24 * 24;   // 4608
constexpr int HW_  = H_ * W_;

typedef unsigned long long ull;

__device__ __forceinline__ ull dup2(float x) {
    ull r; asm("mov.b64 %0,{%1,%1};" : "=l"(r) : "f"(x)); return r;
}
__device__ __forceinline__ void upk2(ull v, float& x, float& y) {
    asm("mov.b64 {%0,%1},%2;" : "=f"(x), "=f"(y) : "l"(v));
}
__device__ __forceinline__ ull ffma2(ull a, ull b, ull c) {
    ull d; asm("fma.rn.f32x2 %0,%1,%2,%3;" : "=l"(d) : "l"(a), "l"(b), "l"(c));
    return d;
}

// Dynamic smem layout (float offsets)
constexpr int F_AS  = 0;                  // as[192][66] = 12672 f (phase B: xs pitch 64)
constexpr int F_QKV = 12672;              // qkv [3][6][64][32] = 36864 f (phase D: wp[192][66])
constexpr int F_WQ  = F_QKV + 36864;      // 49536: wq[192][34] = 6528 f (phase C: tb)
constexpr int F_BQ  = F_WQ + 6528;        // 56064: 576 f
constexpr int F_BP  = F_BQ + 576;         // 56640: 192 f
constexpr int F_TOT = F_BP + 192;         // 56832 floats = 227328 B

// =====================================================================
// Fully fused shifted-window attention: one CTA per window.
// gather -> QKV GEMM -> attention -> proj GEMM -> scatter
// =====================================================================
__global__ __launch_bounds__(256, 1)
void k_fused(const float* __restrict__ x,
             const float* __restrict__ qw, const float* __restrict__ qb,
             const float* __restrict__ pw, const float* __restrict__ pb,
             const float* __restrict__ tbl, float* __restrict__ out) {
    extern __shared__ float sm[];
    float* xs   = sm + F_AS;    // [192][64] in phase B, [192][66] in C/D
    float* qkvs = sm + F_QKV;   // [s][h][n][d]
    float* wq   = sm + F_WQ;    // qkv weight stage; tb during attn
    float* sbq  = sm + F_BQ;
    float* sbp  = sm + F_BP;
    __shared__ int soff[64];
    __shared__ int ids[64];

    const int b_  = blockIdx.x;
    const int b   = b_ / 576;
    const int wh  = (b_ % 576) / 24;
    const int ww  = b_ % 24;
    const int tid = threadIdx.x;
    const int wid = tid >> 5;
    const int lane = tid & 31;

    // ---------------- Phase A: indices, biases, gather ----------------
    if (tid < 64) {
        int ph = tid >> 3, pw2 = tid & 7;
        int sh = wh * 8 + ph + SS_; if (sh >= H_) sh -= H_;
        int sw = ww * 8 + pw2 + SS_; if (sw >= W_) sw -= W_;
        soff[tid] = sh * W_ + sw;
        int gh = wh * 8 + ph, gw = ww * 8 + pw2;
        int rh = gh < (H_ - 8) ? 0 : (gh < (H_ - 4) ? 1 : 2);
        int rw = gw < (W_ - 8) ? 0 : (gw < (W_ - 4) ? 1 : 2);
        ids[tid] = rh * 3 + rw;
    }
    for (int i = tid; i < 576; i += 256) sbq[i] = qb[i];
    if (tid < 192) sbp[tid] = pb[tid];
    __syncthreads();

    const float* xb = x + (size_t)b * C_ * HW_;
    #pragma unroll
    for (int i = 0; i < 48; i++) {
        int idx = tid + i * 256;
        int c = idx >> 6, t = idx & 63;
        xs[c * 64 + t] = xb[c * HW_ + soff[t]];
    }

    // ---------------- Phase B: QKV GEMM (18 chunks of 32 outputs) ----
    const int ty = tid >> 4, tx = tid & 15, t0 = 4 * ty;

    for (int ch = 0; ch < 18; ch++) {
        __syncthreads();   // prior chunk's wq reads done (also covers gather)
        const float* wb = qw + (size_t)ch * 32 * 192;
        #pragma unroll
        for (int i = 0; i < 24; i++) {
            int idx = tid + i * 256;
            int o = idx / 192, k = idx - o * 192;
            wq[k * 34 + o] = wb[o * 192 + k];
        }
        __syncthreads();

        ull acc[4];
        {
            ull bb = *(const ull*)&sbq[ch * 32 + 2 * tx];
            acc[0] = bb; acc[1] = bb; acc[2] = bb; acc[3] = bb;
        }
        #pragma unroll 4
        for (int k = 0; k < 192; k++) {
            float4 af = *(const float4*)&xs[k * 64 + t0];
            ull bv = *(const ull*)&wq[k * 34 + 2 * tx];
            acc[0] = ffma2(dup2(af.x), bv, acc[0]);
            acc[1] = ffma2(dup2(af.y), bv, acc[1]);
            acc[2] = ffma2(dup2(af.z), bv, acc[2]);
            acc[3] = ffma2(dup2(af.w), bv, acc[3]);
        }

        const int s = ch / 6, h = ch - 6 * s;
        const float sc = (s == 0) ? 0.17677669529663687f : 1.0f;
        float* go = qkvs + (size_t)(s * 6 + h) * 2048 + 2 * tx;
        #pragma unroll
        for (int t = 0; t < 4; t++) {
            float xx, yy;
            upk2(acc[t], xx, yy);
            *(float2*)&go[(t0 + t) * 32] = make_float2(xx * sc, yy * sc);
        }
    }

    // ---------------- Phase C: attention (warps 0-5 = heads) --------
    __syncthreads();   // qkvs complete; wq free
    float* tb = wq;    // [6][228]
    for (int i = tid; i < 1350; i += 256) {
        int hh = i % 6, ii = i / 6;
        tb[hh * 228 + ii] = tbl[i];
    }
    __syncthreads();

    if (wid < 6) {
        const int h = wid, r = lane;
        const int rA = r, rB = r + 32;
        const float* qbase = qkvs + (size_t)h * 2048;

        ull qA[16], qB[16];
        {
            const ull* qa = (const ull*)(qbase + (size_t)rA * 32);
            const ull* qb2 = (const ull*)(qbase + (size_t)rB * 32);
            #pragma unroll
            for (int i = 0; i < 16; i++) { qA[i] = qa[i]; qB[i] = qb2[i]; }
        }

        const int baseA = ((rA >> 3) + 7) * 15 + ((rA & 7) + 7);
        const int baseB = ((rB >> 3) + 7) * 15 + ((rB & 7) + 7);
        const int idnA = ids[rA];
        const int idnB = ids[rB];
        const float* tbh = tb + h * 228;

        float sumA = 0.f, sumB = 0.f;
        ull accA[16], accB[16];
        #pragma unroll
        for (int i = 0; i < 16; i++) { accA[i] = 0ull; accB[i] = 0ull; }

        const ulonglong2* ksr = (const ulonglong2*)(qkvs + (size_t)(6 + h) * 2048);
        const ulonglong2* vsr = (const ulonglong2*)(qkvs + (size_t)(12 + h) * 2048);

        #pragma unroll 2
        for (int m = 0; m < 64; m++) {
            const ulonglong2* kk = ksr + m * 8;
            ull dA0 = 0, dA1 = 0, dB0 = 0, dB1 = 0;
            #pragma unroll
            for (int i = 0; i < 8; i++) {
                ulonglong2 kv = kk[i];
                dA0 = ffma2(qA[2 * i],     kv.x, dA0);
                dA1 = ffma2(qA[2 * i + 1], kv.y, dA1);
                dB0 = ffma2(qB[2 * i],     kv.x, dB0);
                dB1 = ffma2(qB[2 * i + 1], kv.y, dB1);
            }
            float a0, a1, a2, a3, b0, b1, b2, b3;
            upk2(dA0, a0, a1); upk2(dA1, a2, a3);
            upk2(dB0, b0, b1); upk2(dB1, b2, b3);
            int moff = (m >> 3) * 15 + (m & 7);
            int idm  = ids[m];
            float svA = (a0 + a1) + (a2 + a3) + tbh[baseA - moff]
                        - (idnA != idm ? 100.0f : 0.0f);
            float svB = (b0 + b1) + (b2 + b3) + tbh[baseB - moff]
                        - (idnB != idm ? 100.0f : 0.0f);
            float eA = __expf(svA), eB = __expf(svB);
            sumA += eA; sumB += eB;
            ull e2A = dup2(eA), e2B = dup2(eB);
            const ulonglong2* vv = vsr + m * 8;
            #pragma unroll
            for (int i = 0; i < 8; i++) {
                ulonglong2 vx = vv[i];
                accA[2 * i]     = ffma2(e2A, vx.x, accA[2 * i]);
                accA[2 * i + 1] = ffma2(e2A, vx.y, accA[2 * i + 1]);
                accB[2 * i]     = ffma2(e2B, vx.x, accB[2 * i]);
                accB[2 * i + 1] = ffma2(e2B, vx.y, accB[2 * i + 1]);
            }
        }

        const float invA = 1.0f / sumA;
        const float invB = 1.0f / sumB;
        // write attn output straight into proj-input layout as[c][66+t]
        float* asb = xs + (h * 32) * 66;
        #pragma unroll
        for (int i = 0; i < 16; i++) {
            float xA, yA, xB, yB;
            upk2(accA[i], xA, yA);
            upk2(accB[i], xB, yB);
            asb[(2 * i) * 66 + rA]     = xA * invA;
            asb[(2 * i + 1) * 66 + rA] = yA * invA;
            asb[(2 * i) * 66 + rB]     = xB * invB;
            asb[(2 * i + 1) * 66 + rB] = yB * invB;
        }
    }

    // ---------------- Phase D: proj GEMM + scatter ------------------
    float* wp = qkvs;   // [192][66], qkv buffer now free
    float* outb = out + (size_t)b * C_ * HW_;

    for (int ch = 0; ch < 3; ch++) {
        __syncthreads();   // attn writes done / prior chunk done
        const float* wb = pw + (size_t)ch * 64 * 192;
        #pragma unroll
        for (int i = 0; i < 48; i++) {
            int idx = tid + i * 256;
            int o = idx / 192, k = idx - o * 192;
            wp[k * 66 + o] = wb[o * 192 + k];
        }
        __syncthreads();

        ull acc[4][2];
        {
            ull b0 = *(const ull*)&sbp[ch * 64 + 2 * tx];
            ull b1 = *(const ull*)&sbp[ch * 64 + 2 * tx + 32];
            #pragma unroll
            for (int t = 0; t < 4; t++) { acc[t][0] = b0; acc[t][1] = b1; }
        }

        #pragma unroll 4
        for (int k = 0; k < 192; k++) {
            const ull* ar = (const ull*)&xs[k * 66 + t0];
            float ax, ay, az, aw;
            upk2(ar[0], ax, ay);
            upk2(ar[1], az, aw);
            ull a0 = dup2(ax), a1 = dup2(ay), a2 = dup2(az), a3 = dup2(aw);
            const ull* wr = (const ull*)&wp[k * 66 + 2 * tx];
            ull bv0 = wr[0], bv1 = wr[16];
            acc[0][0] = ffma2(a0, bv0, acc[0][0]);
            acc[1][0] = ffma2(a1, bv0, acc[1][0]);
            acc[2][0] = ffma2(a2, bv0, acc[2][0]);
            acc[3][0] = ffma2(a3, bv0, acc[3][0]);
            acc[0][1] = ffma2(a0, bv1, acc[0][1]);
            acc[1][1] = ffma2(a1, bv1, acc[1][1]);
            acc[2][1] = ffma2(a2, bv1, acc[2][1]);
            acc[3][1] = ffma2(a3, bv1, acc[3][1]);
        }
        __syncthreads();   // wp weight reads done before res reuse

        float* res = wp;   // [64][66] token-minor staging
        #pragma unroll
        for (int j = 0; j < 2; j++) {
            int ol = 2 * tx + 32 * j;
            #pragma unroll
            for (int t = 0; t < 4; t++) {
                float xx, yy;
                upk2(acc[t][j], xx, yy);
                res[ol * 66 + t0 + t]       = xx;
                res[(ol + 1) * 66 + t0 + t] = yy;
            }
        }
        __syncthreads();

        #pragma unroll
        for (int i = 0; i < 16; i++) {
            int idx = tid + i * 256;
            int o = idx >> 6, t = idx & 63;
            outb[(ch * 64 + o) * HW_ + soff[t]] = res[o * 66 + t];
        }
    }
}

// =====================================================================
extern "C" void kernel_launch(void* const* d_in, const int* in_sizes, int n_in,
                              void* d_out, int out_size) {
    const float* x      = (const float*)d_in[0];
    const float* qkv_w  = (const float*)d_in[1];
    const float* qkv_b  = (const float*)d_in[2];
    const float* proj_w = (const float*)d_in[3];
    const float* proj_b = (const float*)d_in[4];
    const float* tbl    = (const float*)d_in[5];
    float* out = (float*)d_out;

    cudaFuncSetAttribute(k_fused, cudaFuncAttributeMaxDynamicSharedMemorySize,
                         F_TOT * 4);
    k_fused<<<NWIN, 256, F_TOT * 4>>>(x, qkv_w, qkv_b, proj_w, proj_b, tbl, out);
}

// round 12
// speedup vs baseline: 2.5192x; 2.5192x over previous
#include <cuda_runtime.h>
#include <cuda_bf16.h>
#include <cstdint>

constexpr int C_   = 192;
constexpr int H_   = 192;
constexpr int W_   = 192;
constexpr int SS_  = 4;
constexpr int NWIN = 8 * 24 * 24;   // 4608
constexpr int HW_  = H_ * W_;

__device__ float g_qkv[(size_t)NWIN * 3 * 6 * 64 * 32];  // [b_][s][h][n][d]
__device__ float g_att[(size_t)NWIN * 64 * 192];         // [b_*64+n][c]

typedef unsigned long long ull;

__device__ __forceinline__ ull dup2(float x) {
    ull r; asm("mov.b64 %0,{%1,%1};" : "=l"(r) : "f"(x)); return r;
}
__device__ __forceinline__ void upk2(ull v, float& x, float& y) {
    asm("mov.b64 {%0,%1},%2;" : "=f"(x), "=f"(y) : "l"(v));
}
__device__ __forceinline__ ull ffma2(ull a, ull b, ull c) {
    ull d; asm("fma.rn.f32x2 %0,%1,%2,%3;" : "=l"(d) : "l"(a), "l"(b), "l"(c));
    return d;
}
__device__ __forceinline__ uint32_t smem_u32(const void* p) {
    uint32_t a;
    asm("{ .reg .u64 t; cvta.to.shared.u64 t, %1; cvt.u32.u64 %0, t; }"
        : "=r"(a) : "l"(p));
    return a;
}
__device__ __forceinline__ void ldsm4(uint32_t* r, uint32_t addr) {
    asm volatile("ldmatrix.sync.aligned.m8n8.x4.shared.b16 {%0,%1,%2,%3}, [%4];"
                 : "=r"(r[0]), "=r"(r[1]), "=r"(r[2]), "=r"(r[3]) : "r"(addr));
}
__device__ __forceinline__ void mma16816(float* d, const uint32_t* a,
                                         uint32_t b0, uint32_t b1) {
    asm volatile(
        "mma.sync.aligned.m16n8k16.row.col.f32.bf16.bf16.f32 "
        "{%0,%1,%2,%3}, {%4,%5,%6,%7}, {%8,%9}, {%0,%1,%2,%3};"
        : "+f"(d[0]), "+f"(d[1]), "+f"(d[2]), "+f"(d[3])
        : "r"(a[0]), "r"(a[1]), "r"(a[2]), "r"(a[3]), "r"(b0), "r"(b1));
}
__device__ __forceinline__ void split2(float a, float b, uint32_t& hi, uint32_t& lo) {
    __nv_bfloat16 ah = __float2bfloat16(a);
    __nv_bfloat16 bh = __float2bfloat16(b);
    __nv_bfloat16 al = __float2bfloat16(a - __bfloat162float(ah));
    __nv_bfloat16 bl = __float2bfloat16(b - __bfloat162float(bh));
    hi = (uint32_t)__bfloat16_as_ushort(ah) | ((uint32_t)__bfloat16_as_ushort(bh) << 16);
    lo = (uint32_t)__bfloat16_as_ushort(al) | ((uint32_t)__bfloat16_as_ushort(bl) << 16);
}

// smem byte offsets for k_qkv_mma (A/B pitch = 200 bf16 = 400 B)
constexpr int OFF_AHI  = 0;        // 128 x 200 bf16 = 51200
constexpr int OFF_ALO  = 51200;
constexpr int OFF_B    = 102400;   // 2 bufs x (hi 25600 + lo 25600)
constexpr int OFF_BIAS = 204800;   // 576 f
constexpr int SMEM_MMA = 207104;

// =====================================================================
// Kernel 1: QKV GEMM on tensor cores (mma.sync bf16, hi/lo fp32 emu)
// 2 windows/CTA: M=128 tok, K=192, N=576 in 9 chunks of 64.
// grid=2304, block=256 (8 warps; warp w owns m-rows 16w..16w+15).
// =====================================================================
__global__ __launch_bounds__(256, 1)
void k_qkv_mma(const float* __restrict__ x, const float* __restrict__ w,
               const float* __restrict__ bias) {
    extern __shared__ char sm8[];
    const uint32_t sb = smem_u32(sm8);
    float* sbias = (float*)(sm8 + OFF_BIAS);
    __shared__ int soff[128];

    const int bid  = blockIdx.x;
    const int tid  = threadIdx.x;
    const int warp = tid >> 5;
    const int lane = tid & 31;
    const int b    = (2 * bid) / 576;

    if (tid < 128) {
        int win = tid >> 6, t = tid & 63;
        int b_ = 2 * bid + win;
        int wh = (b_ % 576) / 24, ww = b_ % 24;
        int sh = wh * 8 + (t >> 3) + SS_; if (sh >= H_) sh -= H_;
        int sw = ww * 8 + (t & 7)  + SS_; if (sw >= W_) sw -= W_;
        soff[tid] = sh * W_ + sw;
    }
    for (int i = tid; i < 576; i += 256) sbias[i] = bias[i];
    __syncthreads();

    // ---- stage A (gather + hi/lo split), pitch 400 B ----
    const float* xb = x + (size_t)b * C_ * HW_;
    #pragma unroll
    for (int u = 0; u < 12; u++) {
        int idx = tid + u * 256;
        int t = idx & 127, kb = idx >> 7;     // kb: 0..23, 8 k each
        float v[8];
        #pragma unroll
        for (int j = 0; j < 8; j++) v[j] = xb[(kb * 8 + j) * HW_ + soff[t]];
        uint32_t hi[4], lo[4];
        #pragma unroll
        for (int p = 0; p < 4; p++) split2(v[2 * p], v[2 * p + 1], hi[p], lo[p]);
        int byte = t * 400 + kb * 16;
        *(uint4*)(sm8 + OFF_AHI + byte) = make_uint4(hi[0], hi[1], hi[2], hi[3]);
        *(uint4*)(sm8 + OFF_ALO + byte) = make_uint4(lo[0], lo[1], lo[2], lo[3]);
    }

    // ---- B chunk 0: load + store ----
    float wreg[48];
    {
        #pragma unroll
        for (int u = 0; u < 6; u++) {
            int idx = tid + u * 256;
            int nn = idx & 63, kb = idx >> 6;
            const float4* wp4 = (const float4*)(w + (size_t)nn * 192 + kb * 8);
            *(float4*)&wreg[u * 8]     = wp4[0];
            *(float4*)&wreg[u * 8 + 4] = wp4[1];
        }
        #pragma unroll
        for (int u = 0; u < 6; u++) {
            int idx = tid + u * 256;
            int nn = idx & 63, kb = idx >> 6;
            uint32_t hi[4], lo[4];
            #pragma unroll
            for (int p = 0; p < 4; p++)
                split2(wreg[u * 8 + 2 * p], wreg[u * 8 + 2 * p + 1], hi[p], lo[p]);
            int byte = nn * 400 + kb * 16;
            *(uint4*)(sm8 + OFF_B + byte)         = make_uint4(hi[0], hi[1], hi[2], hi[3]);
            *(uint4*)(sm8 + OFF_B + 25600 + byte) = make_uint4(lo[0], lo[1], lo[2], lo[3]);
        }
    }
    __syncthreads();

    const int tt = lane & 7, sel = lane >> 3;
    // ldmatrix address components
    const uint32_t aRow = (uint32_t)(warp * 16 + (sel & 1) * 8 + tt) * 400
                          + (sel >> 1) * 16;
    const uint32_t bRow = (uint32_t)((sel >> 1) * 8 + tt) * 400 + (sel & 1) * 16;
    const int qr = lane >> 2, qc = 2 * (lane & 3);

    for (int ch = 0; ch < 9; ch++) {
        // prefetch next B chunk into regs (overlaps mma)
        if (ch < 8) {
            #pragma unroll
            for (int u = 0; u < 6; u++) {
                int idx = tid + u * 256;
                int nn = idx & 63, kb = idx >> 6;
                const float4* wp4 =
                    (const float4*)(w + (size_t)((ch + 1) * 64 + nn) * 192 + kb * 8);
                *(float4*)&wreg[u * 8]     = wp4[0];
                *(float4*)&wreg[u * 8 + 4] = wp4[1];
            }
        }

        float acc[8][4];
        #pragma unroll
        for (int nt = 0; nt < 8; nt++) {
            float2 bb = *(const float2*)&sbias[ch * 64 + nt * 8 + qc];
            acc[nt][0] = bb.x; acc[nt][1] = bb.y;
            acc[nt][2] = bb.x; acc[nt][3] = bb.y;
        }

        const uint32_t bHI = sb + OFF_B + (uint32_t)(ch & 1) * 51200;
        const uint32_t bLO = bHI + 25600;
        const uint32_t aHI = sb + OFF_AHI + aRow;
        const uint32_t aLO = sb + OFF_ALO + aRow;

        #pragma unroll
        for (int ks = 0; ks < 12; ks++) {
            uint32_t ah[4], al[4];
            ldsm4(ah, aHI + ks * 32);
            ldsm4(al, aLO + ks * 32);
            #pragma unroll
            for (int p = 0; p < 4; p++) {
                uint32_t bh[4], bl[4];
                uint32_t ro = (uint32_t)p * 6400 + bRow + ks * 32;
                ldsm4(bh, bHI + ro);
                ldsm4(bl, bLO + ro);
                mma16816(acc[2 * p],     ah, bh[0], bh[1]);
                mma16816(acc[2 * p],     al, bh[0], bh[1]);
                mma16816(acc[2 * p],     ah, bl[0], bl[1]);
                mma16816(acc[2 * p + 1], ah, bh[2], bh[3]);
                mma16816(acc[2 * p + 1], al, bh[2], bh[3]);
                mma16816(acc[2 * p + 1], ah, bl[2], bl[3]);
            }
        }

        // ---- epilogue: direct global store ----
        const int s  = ch / 3;
        const int r3 = ch - 3 * s;
        const float sc = (s == 0) ? 0.17677669529663687f : 1.0f;
        const int m0  = warp * 16 + qr;         // and m0+8; same window
        const int win = m0 >> 6;
        const int t0  = m0 & 63;
        float* gw = g_qkv + (((size_t)(2 * bid + win) * 3 + s) * 6) * 2048;
        #pragma unroll
        for (int nt = 0; nt < 8; nt++) {
            int off = r3 * 64 + nt * 8 + qc;
            int h = off >> 5, d = off & 31;
            float* gp = gw + (size_t)h * 2048 + d;
            *(float2*)(gp + t0 * 32)       = make_float2(acc[nt][0] * sc, acc[nt][1] * sc);
            *(float2*)(gp + (t0 + 8) * 32) = make_float2(acc[nt][2] * sc, acc[nt][3] * sc);
        }

        // ---- store prefetched B into the other buffer ----
        if (ch < 8) {
            char* dsthi = sm8 + OFF_B + ((ch + 1) & 1) * 51200;
            #pragma unroll
            for (int u = 0; u < 6; u++) {
                int idx = tid + u * 256;
                int nn = idx & 63, kb = idx >> 6;
                uint32_t hi[4], lo[4];
                #pragma unroll
                for (int p = 0; p < 4; p++)
                    split2(wreg[u * 8 + 2 * p], wreg[u * 8 + 2 * p + 1], hi[p], lo[p]);
                int byte = nn * 400 + kb * 16;
                *(uint4*)(dsthi + byte)         = make_uint4(hi[0], hi[1], hi[2], hi[3]);
                *(uint4*)(dsthi + 25600 + byte) = make_uint4(lo[0], lo[1], lo[2], lo[3]);
            }
        }
        __syncthreads();
    }
}

// =====================================================================
// Kernel 2: fused single-pass windowed attention (R2, best known)
// =====================================================================
__global__ __launch_bounds__(192, 2)
void k_attn(const float* __restrict__ tbl) {
    extern __shared__ float sm[];
    float* ks = sm;
    float* vs = sm + 12288;
    float* tb = sm + 24576;
    int*  ids = (int*)(sm + 24576 + 1368);

    const int b_  = blockIdx.x;
    const int wh  = (b_ % 576) / 24;
    const int ww  = b_ % 24;
    const int tid = threadIdx.x;
    const int h   = tid >> 5;
    const int r   = tid & 31;

    const float* base = g_qkv + (size_t)b_ * 3 * 12288;

    {
        const float4* srck = (const float4*)(base + 12288);
        const float4* srcv = (const float4*)(base + 24576);
        float4* dk = (float4*)ks;
        float4* dv = (float4*)vs;
        #pragma unroll
        for (int i = 0; i < 16; i++) {
            int idx = tid + i * 192;
            dk[idx] = srck[idx];
            dv[idx] = srcv[idx];
        }
    }
    for (int i = tid; i < 1350; i += 192) {
        int hh = i % 6, ii = i / 6;
        tb[hh * 228 + ii] = tbl[i];
    }
    if (tid < 64) {
        int ph = tid >> 3, pw = tid & 7;
        int gh = wh * 8 + ph, gw = ww * 8 + pw;
        int rh = gh < (H_ - 8) ? 0 : (gh < (H_ - 4) ? 1 : 2);
        int rw = gw < (W_ - 8) ? 0 : (gw < (W_ - 4) ? 1 : 2);
        ids[tid] = rh * 3 + rw;
    }

    const int rA = r, rB = r + 32;
    ull qA[16], qB[16];
    {
        const ull* qa = (const ull*)(base + (size_t)(h * 64 + rA) * 32);
        const ull* qb = (const ull*)(base + (size_t)(h * 64 + rB) * 32);
        #pragma unroll
        for (int i = 0; i < 16; i++) { qA[i] = qa[i]; qB[i] = qb[i]; }
    }
    __syncthreads();

    const int baseA = ((rA >> 3) + 7) * 15 + ((rA & 7) + 7);
    const int baseB = ((rB >> 3) + 7) * 15 + ((rB & 7) + 7);
    const int idnA = ids[rA];
    const int idnB = ids[rB];
    const float* tbh = tb + h * 228;

    float sumA = 0.f, sumB = 0.f;
    ull accA[16], accB[16];
    #pragma unroll
    for (int i = 0; i < 16; i++) { accA[i] = 0ull; accB[i] = 0ull; }

    const ulonglong2* ksr = (const ulonglong2*)(ks + h * 2048);
    const ulonglong2* vsr = (const ulonglong2*)(vs + h * 2048);

    #pragma unroll 2
    for (int m = 0; m < 64; m++) {
        const ulonglong2* kk = ksr + m * 8;
        ull dA0 = 0, dA1 = 0, dB0 = 0, dB1 = 0;
        #pragma unroll
        for (int i = 0; i < 8; i++) {
            ulonglong2 kv = kk[i];
            dA0 = ffma2(qA[2 * i],     kv.x, dA0);
            dA1 = ffma2(qA[2 * i + 1], kv.y, dA1);
            dB0 = ffma2(qB[2 * i],     kv.x, dB0);
            dB1 = ffma2(qB[2 * i + 1], kv.y, dB1);
        }
        float a0, a1, a2, a3, b0, b1, b2, b3;
        upk2(dA0, a0, a1); upk2(dA1, a2, a3);
        upk2(dB0, b0, b1); upk2(dB1, b2, b3);
        int moff = (m >> 3) * 15 + (m & 7);
        int idm  = ids[m];
        float svA = (a0 + a1) + (a2 + a3) + tbh[baseA - moff]
                    - (idnA != idm ? 100.0f : 0.0f);
        float svB = (b0 + b1) + (b2 + b3) + tbh[baseB - moff]
                    - (idnB != idm ? 100.0f : 0.0f);
        float eA = __expf(svA), eB = __expf(svB);
        sumA += eA; sumB += eB;
        ull e2A = dup2(eA), e2B = dup2(eB);
        const ulonglong2* vv = vsr + m * 8;
        #pragma unroll
        for (int i = 0; i < 8; i++) {
            ulonglong2 vx = vv[i];
            accA[2 * i]     = ffma2(e2A, vx.x, accA[2 * i]);
            accA[2 * i + 1] = ffma2(e2A, vx.y, accA[2 * i + 1]);
            accB[2 * i]     = ffma2(e2B, vx.x, accB[2 * i]);
            accB[2 * i + 1] = ffma2(e2B, vx.y, accB[2 * i + 1]);
        }
    }

    const float invA = 1.0f / sumA;
    const float invB = 1.0f / sumB;
    float* oA = g_att + ((size_t)b_ * 64 + rA) * 192 + h * 32;
    float* oB = g_att + ((size_t)b_ * 64 + rB) * 192 + h * 32;
    #pragma unroll
    for (int i = 0; i < 16; i++) {
        float xx, yy;
        upk2(accA[i], xx, yy);
        *(float2*)&oA[2 * i] = make_float2(xx * invA, yy * invA);
        upk2(accB[i], xx, yy);
        *(float2*)&oB[2 * i] = make_float2(xx * invB, yy * invB);
    }
}

// =====================================================================
// Kernel 3: output projection + reverse roll scatter (R2, best known)
// =====================================================================
__global__ __launch_bounds__(256, 2)
void k_proj(const float* __restrict__ w, const float* __restrict__ bias,
            float* __restrict__ out) {
    extern __shared__ float sm[];
    float* as  = sm;
    float* wsm = sm + 192 * 66;
    __shared__ int soff[64];

    const int b_  = blockIdx.x;
    const int b   = b_ / 576;
    const int wh  = (b_ % 576) / 24;
    const int ww  = b_ % 24;
    const int tid = threadIdx.x;

    if (tid < 64) {
        int ph = tid >> 3, pw = tid & 7;
        int sh = wh * 8 + ph + SS_; if (sh >= H_) sh -= H_;
        int sw = ww * 8 + pw + SS_; if (sw >= W_) sw -= W_;
        soff[tid] = sh * W_ + sw;
    }

    const float* ab = g_att + (size_t)b_ * 64 * 192;
    #pragma unroll
    for (int i = 0; i < 48; i++) {
        int idx = tid + i * 256;
        int t = idx / 192, c = idx - t * 192;
        as[c * 66 + t] = ab[idx];
    }

    const int ty = tid >> 4, tx = tid & 15, t0 = ty * 4;
    float* outb = out + (size_t)b * C_ * HW_;

    for (int ch = 0; ch < 3; ch++) {
        __syncthreads();
        const float* wb = w + ch * 64 * 192;
        #pragma unroll
        for (int i = 0; i < 48; i++) {
            int idx = tid + i * 256;
            int o = idx / 192, k = idx - o * 192;
            wsm[k * 66 + o] = wb[o * 192 + k];
        }
        __syncthreads();

        ull acc[4][2];
        {
            ull b0 = *(const ull*)&bias[ch * 64 + 2 * tx];
            ull b1 = *(const ull*)&bias[ch * 64 + 2 * tx + 32];
            #pragma unroll
            for (int t = 0; t < 4; t++) { acc[t][0] = b0; acc[t][1] = b1; }
        }

        #pragma unroll 4
        for (int k = 0; k < 192; k++) {
            const ull* ar = (const ull*)&as[k * 66 + t0];
            float ax, ay, az, aw;
            upk2(ar[0], ax, ay);
            upk2(ar[1], az, aw);
            ull a0 = dup2(ax), a1 = dup2(ay), a2 = dup2(az), a3 = dup2(aw);
            const ull* wr = (const ull*)&wsm[k * 66 + 2 * tx];
            ull bv0 = wr[0], bv1 = wr[16];
            acc[0][0] = ffma2(a0, bv0, acc[0][0]);
            acc[1][0] = ffma2(a1, bv0, acc[1][0]);
            acc[2][0] = ffma2(a2, bv0, acc[2][0]);
            acc[3][0] = ffma2(a3, bv0, acc[3][0]);
            acc[0][1] = ffma2(a0, bv1, acc[0][1]);
            acc[1][1] = ffma2(a1, bv1, acc[1][1]);
            acc[2][1] = ffma2(a2, bv1, acc[2][1]);
            acc[3][1] = ffma2(a3, bv1, acc[3][1]);
        }
        __syncthreads();

        float* res = wsm;
        #pragma unroll
        for (int j = 0; j < 2; j++) {
            int ol = 2 * tx + 32 * j;
            #pragma unroll
            for (int t = 0; t < 4; t++) {
                float xx, yy;
                upk2(acc[t][j], xx, yy);
                res[ol * 66 + t0 + t]       = xx;
                res[(ol + 1) * 66 + t0 + t] = yy;
            }
        }
        __syncthreads();

        #pragma unroll
        for (int i = 0; i < 16; i++) {
            int idx = tid + i * 256;
            int o = idx >> 6, t = idx & 63;
            outb[(ch * 64 + o) * HW_ + soff[t]] = res[o * 66 + t];
        }
    }
}

// =====================================================================
extern "C" void kernel_launch(void* const* d_in, const int* in_sizes, int n_in,
                              void* d_out, int out_size) {
    const float* x      = (const float*)d_in[0];
    const float* qkv_w  = (const float*)d_in[1];
    const float* qkv_b  = (const float*)d_in[2];
    const float* proj_w = (const float*)d_in[3];
    const float* proj_b = (const float*)d_in[4];
    const float* tbl    = (const float*)d_in[5];
    float* out = (float*)d_out;

    cudaFuncSetAttribute(k_qkv_mma, cudaFuncAttributeMaxDynamicSharedMemorySize, SMEM_MMA);
    cudaFuncSetAttribute(k_attn,    cudaFuncAttributeMaxDynamicSharedMemorySize, 104032);
    cudaFuncSetAttribute(k_proj,    cudaFuncAttributeMaxDynamicSharedMemorySize, 101376);

    k_qkv_mma<<<NWIN / 2, 256, SMEM_MMA>>>(x, qkv_w, qkv_b);
    k_attn<<<NWIN, 192, 104032>>>(tbl);
    k_proj<<<NWIN, 256, 101376>>>(proj_w, proj_b, out);
}

// round 13
// speedup vs baseline: 3.3161x; 1.3164x over previous
#include <cuda_runtime.h>
#include <cuda_bf16.h>
#include <cstdint>

constexpr int C_   = 192;
constexpr int H_   = 192;
constexpr int W_   = 192;
constexpr int SS_  = 4;
constexpr int NWIN = 8 * 24 * 24;   // 4608
constexpr int HW_  = H_ * W_;

__device__ float g_qkv[(size_t)NWIN * 3 * 6 * 64 * 32];  // [b_][s][h][n][d]
__device__ float g_att[(size_t)NWIN * 64 * 192];         // [b_*64+n][c]
// pre-split weights: row-major [row][24 x uint4 of bf16x8]
__device__ uint4 g_wqh[576 * 24], g_wql[576 * 24];
__device__ uint4 g_wph[192 * 24], g_wpl[192 * 24];

typedef unsigned long long ull;

__device__ __forceinline__ ull dup2(float x) {
    ull r; asm("mov.b64 %0,{%1,%1};" : "=l"(r) : "f"(x)); return r;
}
__device__ __forceinline__ void upk2(ull v, float& x, float& y) {
    asm("mov.b64 {%0,%1},%2;" : "=f"(x), "=f"(y) : "l"(v));
}
__device__ __forceinline__ ull ffma2(ull a, ull b, ull c) {
    ull d; asm("fma.rn.f32x2 %0,%1,%2,%3;" : "=l"(d) : "l"(a), "l"(b), "l"(c));
    return d;
}
__device__ __forceinline__ uint32_t smem_u32(const void* p) {
    uint32_t a;
    asm("{ .reg .u64 t; cvta.to.shared.u64 t, %1; cvt.u32.u64 %0, t; }"
        : "=r"(a) : "l"(p));
    return a;
}
__device__ __forceinline__ void ldsm4(uint32_t* r, uint32_t addr) {
    asm volatile("ldmatrix.sync.aligned.m8n8.x4.shared.b16 {%0,%1,%2,%3}, [%4];"
                 : "=r"(r[0]), "=r"(r[1]), "=r"(r[2]), "=r"(r[3]) : "r"(addr));
}
__device__ __forceinline__ void mma16816(float* d, const uint32_t* a,
                                         uint32_t b0, uint32_t b1) {
    asm volatile(
        "mma.sync.aligned.m16n8k16.row.col.f32.bf16.bf16.f32 "
        "{%0,%1,%2,%3}, {%4,%5,%6,%7}, {%8,%9}, {%0,%1,%2,%3};"
        : "+f"(d[0]), "+f"(d[1]), "+f"(d[2]), "+f"(d[3])
        : "r"(a[0]), "r"(a[1]), "r"(a[2]), "r"(a[3]), "r"(b0), "r"(b1));
}
__device__ __forceinline__ void split2(float a, float b, uint32_t& hi, uint32_t& lo) {
    __nv_bfloat16 ah = __float2bfloat16(a);
    __nv_bfloat16 bh = __float2bfloat16(b);
    __nv_bfloat16 al = __float2bfloat16(a - __bfloat162float(ah));
    __nv_bfloat16 bl = __float2bfloat16(b - __bfloat162float(bh));
    hi = (uint32_t)__bfloat16_as_ushort(ah) | ((uint32_t)__bfloat16_as_ushort(bh) << 16);
    lo = (uint32_t)__bfloat16_as_ushort(al) | ((uint32_t)__bfloat16_as_ushort(bl) << 16);
}

// =====================================================================
// Setup: split qkv_w (576x192) + proj_w (192x192) into bf16 hi/lo
// grid=72, block=256: one uint4 (8 elems) per thread.
// =====================================================================
__global__ void k_split_w(const float* __restrict__ qw, const float* __restrict__ pw) {
    int i = blockIdx.x * 256 + threadIdx.x;      // 0 .. 18431
    const float* src;
    uint4 *dh, *dl;
    int base;
    if (i < 13824) { src = qw; dh = g_wqh; dl = g_wql; base = i; }
    else           { src = pw; dh = g_wph; dl = g_wpl; base = i - 13824; }
    int row = base / 24, c = base % 24;
    const float* p = src + row * 192 + c * 8;
    float4 v0 = *(const float4*)p;
    float4 v1 = *(const float4*)(p + 4);
    uint32_t hi[4], lo[4];
    split2(v0.x, v0.y, hi[0], lo[0]);
    split2(v0.z, v0.w, hi[1], lo[1]);
    split2(v1.x, v1.y, hi[2], lo[2]);
    split2(v1.z, v1.w, hi[3], lo[3]);
    dh[base] = make_uint4(hi[0], hi[1], hi[2], hi[3]);
    dl[base] = make_uint4(lo[0], lo[1], lo[2], lo[3]);
}

// smem layout (bytes), pitch 400 B per 192-elem bf16 row
constexpr int Q_AHI  = 0;        // 64 x 400
constexpr int Q_ALO  = 25600;
constexpr int Q_BHI  = 51200;    // 64 x 400 (current chunk)
constexpr int Q_BLO  = 76800;
constexpr int Q_BIAS = 102400;   // 576 f
constexpr int SMEM_Q = 104704;

// =====================================================================
// Kernel 1: QKV GEMM, mma.sync bf16 hi/lo. 1 window/CTA (M=64).
// grid=4608, block=256, 2 CTAs/SM. Warp w: m-block w&3, n-half w>>2.
// =====================================================================
__global__ __launch_bounds__(256, 2)
void k_qkv_mma(const float* __restrict__ x, const float* __restrict__ bias) {
    extern __shared__ char sm8[];
    const uint32_t sb = smem_u32(sm8);
    float* sbias = (float*)(sm8 + Q_BIAS);
    __shared__ int soff[64];

    const int b_   = blockIdx.x;
    const int b    = b_ / 576;
    const int tid  = threadIdx.x;
    const int warp = tid >> 5;
    const int lane = tid & 31;

    if (tid < 64) {
        int wh = (b_ % 576) / 24, ww = b_ % 24;
        int sh = wh * 8 + (tid >> 3) + SS_; if (sh >= H_) sh -= H_;
        int sw = ww * 8 + (tid & 7)  + SS_; if (sw >= W_) sw -= W_;
        soff[tid] = sh * W_ + sw;
    }
    for (int i = tid; i < 576; i += 256) sbias[i] = bias[i];
    __syncthreads();

    // ---- stage A: gather + split (64 tok x 192 c) ----
    const float* xb = x + (size_t)b * C_ * HW_;
    #pragma unroll
    for (int u = 0; u < 6; u++) {
        int idx = tid + u * 256;
        int t = idx & 63, kb = idx >> 6;     // kb: 0..23
        float v[8];
        #pragma unroll
        for (int j = 0; j < 8; j++) v[j] = xb[(kb * 8 + j) * HW_ + soff[t]];
        uint32_t hi[4], lo[4];
        #pragma unroll
        for (int p = 0; p < 4; p++) split2(v[2 * p], v[2 * p + 1], hi[p], lo[p]);
        int byte = t * 400 + kb * 16;
        *(uint4*)(sm8 + Q_AHI + byte) = make_uint4(hi[0], hi[1], hi[2], hi[3]);
        *(uint4*)(sm8 + Q_ALO + byte) = make_uint4(lo[0], lo[1], lo[2], lo[3]);
    }

    const int tt = lane & 7, sel = lane >> 3;
    const int mb = warp & 3, nh = warp >> 2;
    const uint32_t aRow = (uint32_t)(mb * 16 + (sel & 1) * 8 + tt) * 400
                          + (sel >> 1) * 16;
    const uint32_t bRow = (uint32_t)((sel >> 1) * 8 + tt) * 400 + (sel & 1) * 16;
    const int qr = lane >> 2, qc = 2 * (lane & 3);
    const int t0 = mb * 16 + qr;

    for (int ch = 0; ch < 9; ch++) {
        __syncthreads();      // A ready / previous chunk's B reads done
        {   // stage B chunk from pre-split weights (copy only)
            const uint4* srch = g_wqh + (size_t)ch * 64 * 24;
            const uint4* srcl = g_wql + (size_t)ch * 64 * 24;
            #pragma unroll
            for (int u = 0; u < 6; u++) {
                int i = tid + u * 256;           // 0..1535
                int row = i / 24, c = i - row * 24;
                int byte = row * 400 + c * 16;
                *(uint4*)(sm8 + Q_BHI + byte) = srch[i];
                *(uint4*)(sm8 + Q_BLO + byte) = srcl[i];
            }
        }
        __syncthreads();

        float acc[4][4];
        #pragma unroll
        for (int j = 0; j < 4; j++) {
            float2 bb = *(const float2*)&sbias[ch * 64 + nh * 32 + j * 8 + qc];
            acc[j][0] = bb.x; acc[j][1] = bb.y;
            acc[j][2] = bb.x; acc[j][3] = bb.y;
        }

        const uint32_t aHI = sb + Q_AHI + aRow;
        const uint32_t aLO = sb + Q_ALO + aRow;
        const uint32_t bHI = sb + Q_BHI + (uint32_t)nh * 32 * 400 + bRow;
        const uint32_t bLO = sb + Q_BLO + (uint32_t)nh * 32 * 400 + bRow;

        #pragma unroll
        for (int ks = 0; ks < 12; ks++) {
            uint32_t ah[4], al[4];
            ldsm4(ah, aHI + ks * 32);
            ldsm4(al, aLO + ks * 32);
            #pragma unroll
            for (int g = 0; g < 2; g++) {
                uint32_t bh[4], bl[4];
                uint32_t ro = (uint32_t)g * 6400 + ks * 32;
                ldsm4(bh, bHI + ro);
                ldsm4(bl, bLO + ro);
                mma16816(acc[2 * g],     ah, bh[0], bh[1]);
                mma16816(acc[2 * g],     al, bh[0], bh[1]);
                mma16816(acc[2 * g],     ah, bl[0], bl[1]);
                mma16816(acc[2 * g + 1], ah, bh[2], bh[3]);
                mma16816(acc[2 * g + 1], al, bh[2], bh[3]);
                mma16816(acc[2 * g + 1], ah, bl[2], bl[3]);
            }
        }

        // ---- epilogue: direct global store ----
        const int s  = ch / 3;
        const int r3 = ch - 3 * s;
        const int h  = 2 * r3 + nh;
        const float sc = (s == 0) ? 0.17677669529663687f : 1.0f;
        float* gp = g_qkv + (((size_t)b_ * 3 + s) * 6 + h) * 2048;
        #pragma unroll
        for (int nt = 0; nt < 4; nt++) {
            int d = nt * 8 + qc;
            *(float2*)(gp + d + t0 * 32) =
                make_float2(acc[nt][0] * sc, acc[nt][1] * sc);
            *(float2*)(gp + d + (t0 + 8) * 32) =
                make_float2(acc[nt][2] * sc, acc[nt][3] * sc);
        }
    }
}

// =====================================================================
// Kernel 2: fused single-pass windowed attention (R2/R12, best known)
// =====================================================================
__global__ __launch_bounds__(192, 2)
void k_attn(const float* __restrict__ tbl) {
    extern __shared__ float sm[];
    float* ks = sm;
    float* vs = sm + 12288;
    float* tb = sm + 24576;
    int*  ids = (int*)(sm + 24576 + 1368);

    const int b_  = blockIdx.x;
    const int wh  = (b_ % 576) / 24;
    const int ww  = b_ % 24;
    const int tid = threadIdx.x;
    const int h   = tid >> 5;
    const int r   = tid & 31;

    const float* base = g_qkv + (size_t)b_ * 3 * 12288;

    {
        const float4* srck = (const float4*)(base + 12288);
        const float4* srcv = (const float4*)(base + 24576);
        float4* dk = (float4*)ks;
        float4* dv = (float4*)vs;
        #pragma unroll
        for (int i = 0; i < 16; i++) {
            int idx = tid + i * 192;
            dk[idx] = srck[idx];
            dv[idx] = srcv[idx];
        }
    }
    for (int i = tid; i < 1350; i += 192) {
        int hh = i % 6, ii = i / 6;
        tb[hh * 228 + ii] = tbl[i];
    }
    if (tid < 64) {
        int ph = tid >> 3, pw = tid & 7;
        int gh = wh * 8 + ph, gw = ww * 8 + pw;
        int rh = gh < (H_ - 8) ? 0 : (gh < (H_ - 4) ? 1 : 2);
        int rw = gw < (W_ - 8) ? 0 : (gw < (W_ - 4) ? 1 : 2);
        ids[tid] = rh * 3 + rw;
    }

    const int rA = r, rB = r + 32;
    ull qA[16], qB[16];
    {
        const ull* qa = (const ull*)(base + (size_t)(h * 64 + rA) * 32);
        const ull* qb = (const ull*)(base + (size_t)(h * 64 + rB) * 32);
        #pragma unroll
        for (int i = 0; i < 16; i++) { qA[i] = qa[i]; qB[i] = qb[i]; }
    }
    __syncthreads();

    const int baseA = ((rA >> 3) + 7) * 15 + ((rA & 7) + 7);
    const int baseB = ((rB >> 3) + 7) * 15 + ((rB & 7) + 7);
    const int idnA = ids[rA];
    const int idnB = ids[rB];
    const float* tbh = tb + h * 228;

    float sumA = 0.f, sumB = 0.f;
    ull accA[16], accB[16];
    #pragma unroll
    for (int i = 0; i < 16; i++) { accA[i] = 0ull; accB[i] = 0ull; }

    const ulonglong2* ksr = (const ulonglong2*)(ks + h * 2048);
    const ulonglong2* vsr = (const ulonglong2*)(vs + h * 2048);

    #pragma unroll 2
    for (int m = 0; m < 64; m++) {
        const ulonglong2* kk = ksr + m * 8;
        ull dA0 = 0, dA1 = 0, dB0 = 0, dB1 = 0;
        #pragma unroll
        for (int i = 0; i < 8; i++) {
            ulonglong2 kv = kk[i];
            dA0 = ffma2(qA[2 * i],     kv.x, dA0);
            dA1 = ffma2(qA[2 * i + 1], kv.y, dA1);
            dB0 = ffma2(qB[2 * i],     kv.x, dB0);
            dB1 = ffma2(qB[2 * i + 1], kv.y, dB1);
        }
        float a0, a1, a2, a3, b0, b1, b2, b3;
        upk2(dA0, a0, a1); upk2(dA1, a2, a3);
        upk2(dB0, b0, b1); upk2(dB1, b2, b3);
        int moff = (m >> 3) * 15 + (m & 7);
        int idm  = ids[m];
        float svA = (a0 + a1) + (a2 + a3) + tbh[baseA - moff]
                    - (idnA != idm ? 100.0f : 0.0f);
        float svB = (b0 + b1) + (b2 + b3) + tbh[baseB - moff]
                    - (idnB != idm ? 100.0f : 0.0f);
        float eA = __expf(svA), eB = __expf(svB);
        sumA += eA; sumB += eB;
        ull e2A = dup2(eA), e2B = dup2(eB);
        const ulonglong2* vv = vsr + m * 8;
        #pragma unroll
        for (int i = 0; i < 8; i++) {
            ulonglong2 vx = vv[i];
            accA[2 * i]     = ffma2(e2A, vx.x, accA[2 * i]);
            accA[2 * i + 1] = ffma2(e2A, vx.y, accA[2 * i + 1]);
            accB[2 * i]     = ffma2(e2B, vx.x, accB[2 * i]);
            accB[2 * i + 1] = ffma2(e2B, vx.y, accB[2 * i + 1]);
        }
    }

    const float invA = 1.0f / sumA;
    const float invB = 1.0f / sumB;
    float* oA = g_att + ((size_t)b_ * 64 + rA) * 192 + h * 32;
    float* oB = g_att + ((size_t)b_ * 64 + rB) * 192 + h * 32;
    #pragma unroll
    for (int i = 0; i < 16; i++) {
        float xx, yy;
        upk2(accA[i], xx, yy);
        *(float2*)&oA[2 * i] = make_float2(xx * invA, yy * invA);
        upk2(accB[i], xx, yy);
        *(float2*)&oB[2 * i] = make_float2(xx * invB, yy * invB);
    }
}

// smem layout for k_proj_mma
constexpr int P_AHI  = 0;
constexpr int P_ALO  = 25600;
constexpr int P_BHI  = 51200;    // also res[64][66] staging after mma
constexpr int P_BLO  = 76800;
constexpr int P_BIAS = 102400;   // 192 f
constexpr int SMEM_P = 103168;

// =====================================================================
// Kernel 3: proj GEMM on mma.sync + reverse-roll scatter.
// grid=4608, block=256, 2 CTAs/SM. 3 chunks of 64 outputs.
// =====================================================================
__global__ __launch_bounds__(256, 2)
void k_proj_mma(const float* __restrict__ bias, float* __restrict__ out) {
    extern __shared__ char sm8[];
    const uint32_t sb = smem_u32(sm8);
    float* sbias = (float*)(sm8 + P_BIAS);
    float* res   = (float*)(sm8 + P_BHI);    // overlays B_hi after mma
    __shared__ int soff[64];

    const int b_   = blockIdx.x;
    const int b    = b_ / 576;
    const int tid  = threadIdx.x;
    const int warp = tid >> 5;
    const int lane = tid & 31;

    if (tid < 64) {
        int wh = (b_ % 576) / 24, ww = b_ % 24;
        int sh = wh * 8 + (tid >> 3) + SS_; if (sh >= H_) sh -= H_;
        int sw = ww * 8 + (tid & 7)  + SS_; if (sw >= W_) sw -= W_;
        soff[tid] = sh * W_ + sw;
    }
    if (tid < 192) sbias[tid] = bias[tid];

    // ---- stage A: attention output (64 tok x 192 c), coalesced ----
    const float* ab = g_att + (size_t)b_ * 64 * 192;
    #pragma unroll
    for (int u = 0; u < 6; u++) {
        int i = tid + u * 256;
        int t = i / 24, kb = i - t * 24;
        const float4* p = (const float4*)(ab + t * 192 + kb * 8);
        float4 v0 = p[0], v1 = p[1];
        uint32_t hi[4], lo[4];
        split2(v0.x, v0.y, hi[0], lo[0]);
        split2(v0.z, v0.w, hi[1], lo[1]);
        split2(v1.x, v1.y, hi[2], lo[2]);
        split2(v1.z, v1.w, hi[3], lo[3]);
        int byte = t * 400 + kb * 16;
        *(uint4*)(sm8 + P_AHI + byte) = make_uint4(hi[0], hi[1], hi[2], hi[3]);
        *(uint4*)(sm8 + P_ALO + byte) = make_uint4(lo[0], lo[1], lo[2], lo[3]);
    }

    const int tt = lane & 7, sel = lane >> 3;
    const int mb = warp & 3, nh = warp >> 2;
    const uint32_t aRow = (uint32_t)(mb * 16 + (sel & 1) * 8 + tt) * 400
                          + (sel >> 1) * 16;
    const uint32_t bRow = (uint32_t)((sel >> 1) * 8 + tt) * 400 + (sel & 1) * 16;
    const int qr = lane >> 2, qc = 2 * (lane & 3);
    const int t0 = mb * 16 + qr;
    float* outb = out + (size_t)b * C_ * HW_;

    for (int ch = 0; ch < 3; ch++) {
        __syncthreads();      // A ready / prev scatter done
        {
            const uint4* srch = g_wph + (size_t)ch * 64 * 24;
            const uint4* srcl = g_wpl + (size_t)ch * 64 * 24;
            #pragma unroll
            for (int u = 0; u < 6; u++) {
                int i = tid + u * 256;
                int row = i / 24, c = i - row * 24;
                int byte = row * 400 + c * 16;
                *(uint4*)(sm8 + P_BHI + byte) = srch[i];
                *(uint4*)(sm8 + P_BLO + byte) = srcl[i];
            }
        }
        __syncthreads();

        float acc[4][4];
        #pragma unroll
        for (int j = 0; j < 4; j++) {
            float2 bb = *(const float2*)&sbias[ch * 64 + nh * 32 + j * 8 + qc];
            acc[j][0] = bb.x; acc[j][1] = bb.y;
            acc[j][2] = bb.x; acc[j][3] = bb.y;
        }

        const uint32_t aHI = sb + P_AHI + aRow;
        const uint32_t aLO = sb + P_ALO + aRow;
        const uint32_t bHI = sb + P_BHI + (uint32_t)nh * 32 * 400 + bRow;
        const uint32_t bLO = sb + P_BLO + (uint32_t)nh * 32 * 400 + bRow;

        #pragma unroll
        for (int ks = 0; ks < 12; ks++) {
            uint32_t ah[4], al[4];
            ldsm4(ah, aHI + ks * 32);
            ldsm4(al, aLO + ks * 32);
            #pragma unroll
            for (int g = 0; g < 2; g++) {
                uint32_t bh[4], bl[4];
                uint32_t ro = (uint32_t)g * 6400 + ks * 32;
                ldsm4(bh, bHI + ro);
                ldsm4(bl, bLO + ro);
                mma16816(acc[2 * g],     ah, bh[0], bh[1]);
                mma16816(acc[2 * g],     al, bh[0], bh[1]);
                mma16816(acc[2 * g],     ah, bl[0], bl[1]);
                mma16816(acc[2 * g + 1], ah, bh[2], bh[3]);
                mma16816(acc[2 * g + 1], al, bh[2], bh[3]);
                mma16816(acc[2 * g + 1], ah, bl[2], bl[3]);
            }
        }
        __syncthreads();      // all B reads done before res overlay

        // ---- stage res[64 o][66 t] ----
        #pragma unroll
        for (int j = 0; j < 4; j++) {
            int o = nh * 32 + j * 8 + qc;
            res[o * 66 + t0]           = acc[j][0];
            res[(o + 1) * 66 + t0]     = acc[j][1];
            res[o * 66 + t0 + 8]       = acc[j][2];
            res[(o + 1) * 66 + t0 + 8] = acc[j][3];
        }
        __syncthreads();

        #pragma unroll
        for (int i = 0; i < 16; i++) {
            int idx = tid + i * 256;
            int o = idx >> 6, t = idx & 63;
            outb[(ch * 64 + o) * HW_ + soff[t]] = res[o * 66 + t];
        }
    }
}

// =====================================================================
extern "C" void kernel_launch(void* const* d_in, const int* in_sizes, int n_in,
                              void* d_out, int out_size) {
    const float* x      = (const float*)d_in[0];
    const float* qkv_w  = (const float*)d_in[1];
    const float* qkv_b  = (const float*)d_in[2];
    const float* proj_w = (const float*)d_in[3];
    const float* proj_b = (const float*)d_in[4];
    const float* tbl    = (const float*)d_in[5];
    float* out = (float*)d_out;

    cudaFuncSetAttribute(k_qkv_mma,  cudaFuncAttributeMaxDynamicSharedMemorySize, SMEM_Q);
    cudaFuncSetAttribute(k_attn,     cudaFuncAttributeMaxDynamicSharedMemorySize, 104032);
    cudaFuncSetAttribute(k_proj_mma, cudaFuncAttributeMaxDynamicSharedMemorySize, SMEM_P);

    k_split_w<<<72, 256>>>(qkv_w, proj_w);
    k_qkv_mma<<<NWIN, 256, SMEM_Q>>>(x, qkv_b);
    k_attn<<<NWIN, 192, 104032>>>(tbl);
    k_proj_mma<<<NWIN, 256, SMEM_P>>>(proj_b, out);
}

// round 14
// speedup vs baseline: 3.5890x; 1.0823x over previous
#include <cuda_runtime.h>
#include <cuda_bf16.h>
#include <cstdint>

constexpr int C_   = 192;
constexpr int H_   = 192;
constexpr int W_   = 192;
constexpr int SS_  = 4;
constexpr int NWIN = 8 * 24 * 24;   // 4608
constexpr int HW_  = H_ * W_;

__device__ float g_qkv[(size_t)NWIN * 3 * 6 * 64 * 32];  // [b_][s][h][n][d]
// pre-split weights / activations: [row][24] uint4 (8 bf16 each)
__device__ uint4 g_wqh[576 * 24], g_wql[576 * 24];
__device__ uint4 g_wph[192 * 24], g_wpl[192 * 24];
__device__ uint4 g_xhi[(size_t)NWIN * 1536], g_xlo[(size_t)NWIN * 1536];
__device__ uint4 g_ahi[(size_t)NWIN * 1536], g_alo[(size_t)NWIN * 1536];

typedef unsigned long long ull;

__device__ __forceinline__ ull dup2(float x) {
    ull r; asm("mov.b64 %0,{%1,%1};" : "=l"(r) : "f"(x)); return r;
}
__device__ __forceinline__ void upk2(ull v, float& x, float& y) {
    asm("mov.b64 {%0,%1},%2;" : "=f"(x), "=f"(y) : "l"(v));
}
__device__ __forceinline__ ull ffma2(ull a, ull b, ull c) {
    ull d; asm("fma.rn.f32x2 %0,%1,%2,%3;" : "=l"(d) : "l"(a), "l"(b), "l"(c));
    return d;
}
__device__ __forceinline__ uint32_t smem_u32(const void* p) {
    uint32_t a;
    asm("{ .reg .u64 t; cvta.to.shared.u64 t, %1; cvt.u32.u64 %0, t; }"
        : "=r"(a) : "l"(p));
    return a;
}
__device__ __forceinline__ void ldsm4(uint32_t* r, uint32_t addr) {
    asm volatile("ldmatrix.sync.aligned.m8n8.x4.shared.b16 {%0,%1,%2,%3}, [%4];"
                 : "=r"(r[0]), "=r"(r[1]), "=r"(r[2]), "=r"(r[3]) : "r"(addr));
}
__device__ __forceinline__ void mma16816(float* d, const uint32_t* a,
                                         uint32_t b0, uint32_t b1) {
    asm volatile(
        "mma.sync.aligned.m16n8k16.row.col.f32.bf16.bf16.f32 "
        "{%0,%1,%2,%3}, {%4,%5,%6,%7}, {%8,%9}, {%0,%1,%2,%3};"
        : "+f"(d[0]), "+f"(d[1]), "+f"(d[2]), "+f"(d[3])
        : "r"(a[0]), "r"(a[1]), "r"(a[2]), "r"(a[3]), "r"(b0), "r"(b1));
}
__device__ __forceinline__ void split2(float a, float b, uint32_t& hi, uint32_t& lo) {
    __nv_bfloat16 ah = __float2bfloat16(a);
    __nv_bfloat16 bh = __float2bfloat16(b);
    __nv_bfloat16 al = __float2bfloat16(a - __bfloat162float(ah));
    __nv_bfloat16 bl = __float2bfloat16(b - __bfloat162float(bh));
    hi = (uint32_t)__bfloat16_as_ushort(ah) | ((uint32_t)__bfloat16_as_ushort(bh) << 16);
    lo = (uint32_t)__bfloat16_as_ushort(al) | ((uint32_t)__bfloat16_as_ushort(bl) << 16);
}

#define CP_ASYNC16(dst, src) \
    asm volatile("cp.async.cg.shared.global [%0], [%1], 16;" :: "r"(dst), "l"(src))
#define CP_COMMIT() asm volatile("cp.async.commit_group;" ::: "memory")
#define CP_WAIT0()  asm volatile("cp.async.wait_group 0;"  ::: "memory")

// =====================================================================
// Setup A: split weights into bf16 hi/lo
// =====================================================================
__global__ void k_split_w(const float* __restrict__ qw, const float* __restrict__ pw) {
    int i = blockIdx.x * 256 + threadIdx.x;      // 0 .. 18431
    const float* src;
    uint4 *dh, *dl;
    int base;
    if (i < 13824) { src = qw; dh = g_wqh; dl = g_wql; base = i; }
    else           { src = pw; dh = g_wph; dl = g_wpl; base = i - 13824; }
    int row = base / 24, c = base % 24;
    const float* p = src + row * 192 + c * 8;
    float4 v0 = *(const float4*)p;
    float4 v1 = *(const float4*)(p + 4);
    uint32_t hi[4], lo[4];
    split2(v0.x, v0.y, hi[0], lo[0]);
    split2(v0.z, v0.w, hi[1], lo[1]);
    split2(v1.x, v1.y, hi[2], lo[2]);
    split2(v1.z, v1.w, hi[3], lo[3]);
    dh[base] = make_uint4(hi[0], hi[1], hi[2], hi[3]);
    dl[base] = make_uint4(lo[0], lo[1], lo[2], lo[3]);
}

// =====================================================================
// Setup B: gather rolled windows + split x into bf16 hi/lo panels
// grid=4608, block=256. Panel layout: [t(64)][kb(24)] uint4.
// =====================================================================
__global__ __launch_bounds__(256)
void k_split_x(const float* __restrict__ x) {
    __shared__ int soff[64];
    const int b_  = blockIdx.x;
    const int b   = b_ / 576;
    const int tid = threadIdx.x;
    if (tid < 64) {
        int wh = (b_ % 576) / 24, ww = b_ % 24;
        int sh = wh * 8 + (tid >> 3) + SS_; if (sh >= H_) sh -= H_;
        int sw = ww * 8 + (tid & 7)  + SS_; if (sw >= W_) sw -= W_;
        soff[tid] = sh * W_ + sw;
    }
    __syncthreads();
    const float* xb = x + (size_t)b * C_ * HW_;
    uint4* dh = g_xhi + (size_t)b_ * 1536;
    uint4* dl = g_xlo + (size_t)b_ * 1536;
    #pragma unroll
    for (int u = 0; u < 6; u++) {
        int i = tid + u * 256;
        int t = i / 24, c = i - t * 24;
        float v[8];
        #pragma unroll
        for (int j = 0; j < 8; j++) v[j] = xb[(c * 8 + j) * HW_ + soff[t]];
        uint32_t hi[4], lo[4];
        #pragma unroll
        for (int p = 0; p < 4; p++) split2(v[2 * p], v[2 * p + 1], hi[p], lo[p]);
        dh[i] = make_uint4(hi[0], hi[1], hi[2], hi[3]);
        dl[i] = make_uint4(lo[0], lo[1], lo[2], lo[3]);
    }
}

// =====================================================================
// Kernel 1: chunk-persistent QKV GEMM.
// grid=(32 groups, 9 chunks), block=256, 1 CTA/SM. W=144 windows/CTA.
// B fragments live in registers; A double-buffered via cp.async.
// smem: 2 bufs x (hi 25600 + lo 25600) = 102400 B.
// =====================================================================
constexpr int QP_W  = 144;
constexpr int QP_NG = 32;

__global__ __launch_bounds__(256, 1)
void k_qkv_pers(const float* __restrict__ bias) {
    extern __shared__ char sm8[];
    const uint32_t sb = smem_u32(sm8);
    const int chunk = blockIdx.y;
    const int grp   = blockIdx.x;
    const int tid = threadIdx.x, warp = tid >> 5, lane = tid & 31;
    const int tt = lane & 7, sel = lane >> 3;
    const int mh = warp & 1, nq = warp >> 1;
    const int qr = lane >> 2, qc = 2 * (lane & 3);

    // ---- stage B chunk into buf1, extract fragments to registers ----
    {
        const uint4* srch = g_wqh + (size_t)chunk * 1536;
        const uint4* srcl = g_wql + (size_t)chunk * 1536;
        #pragma unroll
        for (int u = 0; u < 6; u++) {
            int i = tid + u * 256;
            int row = i / 24, c = i - row * 24;
            *(uint4*)(sm8 + 51200 + row * 400 + c * 16)         = srch[i];
            *(uint4*)(sm8 + 51200 + 25600 + row * 400 + c * 16) = srcl[i];
        }
    }
    __syncthreads();
    uint32_t Bh[12][4], Bl[12][4];
    {
        const uint32_t bRow = (uint32_t)(nq * 16 + (sel >> 1) * 8 + tt) * 400
                              + (sel & 1) * 16;
        uint32_t bH = sb + 51200 + bRow;
        #pragma unroll
        for (int ks = 0; ks < 12; ks++) {
            ldsm4(Bh[ks], bH + ks * 32);
            ldsm4(Bl[ks], bH + 25600 + ks * 32);
        }
    }

    const int s  = chunk / 3, r3 = chunk - 3 * s;
    const int h  = 2 * r3 + (nq >> 1);
    const int dbase = (nq & 1) * 16;
    const float sc = (s == 0) ? 0.17677669529663687f : 1.0f;
    float2 bias0 = *(const float2*)&bias[chunk * 64 + nq * 16 + qc];
    float2 bias1 = *(const float2*)&bias[chunk * 64 + nq * 16 + 8 + qc];

    const int win0 = grp * QP_W;
    // prefetch A(w0) -> buf0
    {
        const uint4* sh2 = g_xhi + (size_t)win0 * 1536;
        const uint4* sl2 = g_xlo + (size_t)win0 * 1536;
        #pragma unroll
        for (int u = 0; u < 6; u++) {
            int i = tid + u * 256;
            int t = i / 24, c = i - t * 24;
            CP_ASYNC16(sb + t * 400 + c * 16,         (const void*)(sh2 + i));
            CP_ASYNC16(sb + 25600 + t * 400 + c * 16, (const void*)(sl2 + i));
        }
        CP_COMMIT();
    }

    for (int i = 0; i < QP_W; i++) {
        const int win = win0 + i;
        CP_WAIT0();
        __syncthreads();     // A(i) visible; all warps done with previous buf
        if (i + 1 < QP_W) {
            uint32_t nb = sb + (uint32_t)((i + 1) & 1) * 51200;
            const uint4* sh2 = g_xhi + (size_t)(win + 1) * 1536;
            const uint4* sl2 = g_xlo + (size_t)(win + 1) * 1536;
            #pragma unroll
            for (int u = 0; u < 6; u++) {
                int ii = tid + u * 256;
                int t = ii / 24, c = ii - t * 24;
                CP_ASYNC16(nb + t * 400 + c * 16,         (const void*)(sh2 + ii));
                CP_ASYNC16(nb + 25600 + t * 400 + c * 16, (const void*)(sl2 + ii));
            }
        }
        CP_COMMIT();

        float acc[2][2][4];
        #pragma unroll
        for (int mt = 0; mt < 2; mt++) {
            acc[mt][0][0] = bias0.x; acc[mt][0][1] = bias0.y;
            acc[mt][0][2] = bias0.x; acc[mt][0][3] = bias0.y;
            acc[mt][1][0] = bias1.x; acc[mt][1][1] = bias1.y;
            acc[mt][1][2] = bias1.x; acc[mt][1][3] = bias1.y;
        }

        const uint32_t abase = sb + (uint32_t)(i & 1) * 51200;
        #pragma unroll
        for (int ks = 0; ks < 12; ks++) {
            #pragma unroll
            for (int mt = 0; mt < 2; mt++) {
                uint32_t ar = abase
                    + (uint32_t)(mh * 32 + mt * 16 + (sel & 1) * 8 + tt) * 400
                    + (sel >> 1) * 16 + ks * 32;
                uint32_t ah[4], al[4];
                ldsm4(ah, ar);
                ldsm4(al, ar + 25600);
                mma16816(acc[mt][0], ah, Bh[ks][0], Bh[ks][1]);
                mma16816(acc[mt][0], al, Bh[ks][0], Bh[ks][1]);
                mma16816(acc[mt][0], ah, Bl[ks][0], Bl[ks][1]);
                mma16816(acc[mt][1], ah, Bh[ks][2], Bh[ks][3]);
                mma16816(acc[mt][1], al, Bh[ks][2], Bh[ks][3]);
                mma16816(acc[mt][1], ah, Bl[ks][2], Bl[ks][3]);
            }
        }

        float* gp = g_qkv + (((size_t)win * 3 + s) * 6 + h) * 2048 + dbase;
        #pragma unroll
        for (int mt = 0; mt < 2; mt++) {
            int t0 = mh * 32 + mt * 16 + qr;
            #pragma unroll
            for (int nt = 0; nt < 2; nt++) {
                int d = nt * 8 + qc;
                *(float2*)(gp + d + t0 * 32) =
                    make_float2(acc[mt][nt][0] * sc, acc[mt][nt][1] * sc);
                *(float2*)(gp + d + (t0 + 8) * 32) =
                    make_float2(acc[mt][nt][2] * sc, acc[mt][nt][3] * sc);
            }
        }
    }
}

// =====================================================================
// Kernel 2: fused single-pass windowed attention.
// Epilogue writes bf16 hi/lo panels for the proj kernel.
// =====================================================================
__global__ __launch_bounds__(192, 2)
void k_attn(const float* __restrict__ tbl) {
    extern __shared__ float sm[];
    float* ks = sm;
    float* vs = sm + 12288;
    float* tb = sm + 24576;
    int*  ids = (int*)(sm + 24576 + 1368);

    const int b_  = blockIdx.x;
    const int wh  = (b_ % 576) / 24;
    const int ww  = b_ % 24;
    const int tid = threadIdx.x;
    const int h   = tid >> 5;
    const int r   = tid & 31;

    const float* base = g_qkv + (size_t)b_ * 3 * 12288;

    {
        const float4* srck = (const float4*)(base + 12288);
        const float4* srcv = (const float4*)(base + 24576);
        float4* dk = (float4*)ks;
        float4* dv = (float4*)vs;
        #pragma unroll
        for (int i = 0; i < 16; i++) {
            int idx = tid + i * 192;
            dk[idx] = srck[idx];
            dv[idx] = srcv[idx];
        }
    }
    for (int i = tid; i < 1350; i += 192) {
        int hh = i % 6, ii = i / 6;
        tb[hh * 228 + ii] = tbl[i];
    }
    if (tid < 64) {
        int ph = tid >> 3, pw = tid & 7;
        int gh = wh * 8 + ph, gw = ww * 8 + pw;
        int rh = gh < (H_ - 8) ? 0 : (gh < (H_ - 4) ? 1 : 2);
        int rw = gw < (W_ - 8) ? 0 : (gw < (W_ - 4) ? 1 : 2);
        ids[tid] = rh * 3 + rw;
    }

    const int rA = r, rB = r + 32;
    ull qA[16], qB[16];
    {
        const ull* qa = (const ull*)(base + (size_t)(h * 64 + rA) * 32);
        const ull* qb = (const ull*)(base + (size_t)(h * 64 + rB) * 32);
        #pragma unroll
        for (int i = 0; i < 16; i++) { qA[i] = qa[i]; qB[i] = qb[i]; }
    }
    __syncthreads();

    const int baseA = ((rA >> 3) + 7) * 15 + ((rA & 7) + 7);
    const int baseB = ((rB >> 3) + 7) * 15 + ((rB & 7) + 7);
    const int idnA = ids[rA];
    const int idnB = ids[rB];
    const float* tbh = tb + h * 228;

    float sumA = 0.f, sumB = 0.f;
    ull accA[16], accB[16];
    #pragma unroll
    for (int i = 0; i < 16; i++) { accA[i] = 0ull; accB[i] = 0ull; }

    const ulonglong2* ksr = (const ulonglong2*)(ks + h * 2048);
    const ulonglong2* vsr = (const ulonglong2*)(vs + h * 2048);

    #pragma unroll 2
    for (int m = 0; m < 64; m++) {
        const ulonglong2* kk = ksr + m * 8;
        ull dA0 = 0, dA1 = 0, dB0 = 0, dB1 = 0;
        #pragma unroll
        for (int i = 0; i < 8; i++) {
            ulonglong2 kv = kk[i];
            dA0 = ffma2(qA[2 * i],     kv.x, dA0);
            dA1 = ffma2(qA[2 * i + 1], kv.y, dA1);
            dB0 = ffma2(qB[2 * i],     kv.x, dB0);
            dB1 = ffma2(qB[2 * i + 1], kv.y, dB1);
        }
        float a0, a1, a2, a3, b0, b1, b2, b3;
        upk2(dA0, a0, a1); upk2(dA1, a2, a3);
        upk2(dB0, b0, b1); upk2(dB1, b2, b3);
        int moff = (m >> 3) * 15 + (m & 7);
        int idm  = ids[m];
        float svA = (a0 + a1) + (a2 + a3) + tbh[baseA - moff]
                    - (idnA != idm ? 100.0f : 0.0f);
        float svB = (b0 + b1) + (b2 + b3) + tbh[baseB - moff]
                    - (idnB != idm ? 100.0f : 0.0f);
        float eA = __expf(svA), eB = __expf(svB);
        sumA += eA; sumB += eB;
        ull e2A = dup2(eA), e2B = dup2(eB);
        const ulonglong2* vv = vsr + m * 8;
        #pragma unroll
        for (int i = 0; i < 8; i++) {
            ulonglong2 vx = vv[i];
            accA[2 * i]     = ffma2(e2A, vx.x, accA[2 * i]);
            accA[2 * i + 1] = ffma2(e2A, vx.y, accA[2 * i + 1]);
            accB[2 * i]     = ffma2(e2B, vx.x, accB[2 * i]);
            accB[2 * i + 1] = ffma2(e2B, vx.y, accB[2 * i + 1]);
        }
    }

    const float invA = 1.0f / sumA;
    const float invB = 1.0f / sumB;
    float oA[32], oB[32];
    #pragma unroll
    for (int i = 0; i < 16; i++) {
        upk2(accA[i], oA[2 * i], oA[2 * i + 1]);
        oA[2 * i] *= invA; oA[2 * i + 1] *= invA;
        upk2(accB[i], oB[2 * i], oB[2 * i + 1]);
        oB[2 * i] *= invB; oB[2 * i + 1] *= invB;
    }
    uint4* dh = g_ahi + (size_t)b_ * 1536;
    uint4* dl = g_alo + (size_t)b_ * 1536;
    #pragma unroll
    for (int j = 0; j < 4; j++) {
        uint32_t h4[4], l4[4];
        #pragma unroll
        for (int p = 0; p < 4; p++)
            split2(oA[8 * j + 2 * p], oA[8 * j + 2 * p + 1], h4[p], l4[p]);
        dh[rA * 24 + h * 4 + j] = make_uint4(h4[0], h4[1], h4[2], h4[3]);
        dl[rA * 24 + h * 4 + j] = make_uint4(l4[0], l4[1], l4[2], l4[3]);
        #pragma unroll
        for (int p = 0; p < 4; p++)
            split2(oB[8 * j + 2 * p], oB[8 * j + 2 * p + 1], h4[p], l4[p]);
        dh[rB * 24 + h * 4 + j] = make_uint4(h4[0], h4[1], h4[2], h4[3]);
        dl[rB * 24 + h * 4 + j] = make_uint4(l4[0], l4[1], l4[2], l4[3]);
    }
}

// =====================================================================
// Kernel 3: chunk-persistent proj GEMM + reverse-roll scatter.
// grid=(96 groups, 3 chunks), block=256, W=48 windows/CTA.
// smem: 2 x 51200 (A bufs) + res 16896 = 119296 B.
// =====================================================================
constexpr int PP_W  = 48;
constexpr int PP_NG = 96;

__global__ __launch_bounds__(256, 1)
void k_proj_pers(const float* __restrict__ bias, float* __restrict__ out) {
    extern __shared__ char sm8[];
    const uint32_t sb = smem_u32(sm8);
    float* res = (float*)(sm8 + 102400);   // [64 o][66 t]
    __shared__ int soff[64];
    const int chunk = blockIdx.y;
    const int grp   = blockIdx.x;
    const int tid = threadIdx.x, warp = tid >> 5, lane = tid & 31;
    const int tt = lane & 7, sel = lane >> 3;
    const int mh = warp & 1, nq = warp >> 1;
    const int qr = lane >> 2, qc = 2 * (lane & 3);

    // stage B chunk into buf1, extract fragments
    {
        const uint4* srch = g_wph + (size_t)chunk * 1536;
        const uint4* srcl = g_wpl + (size_t)chunk * 1536;
        #pragma unroll
        for (int u = 0; u < 6; u++) {
            int i = tid + u * 256;
            int row = i / 24, c = i - row * 24;
            *(uint4*)(sm8 + 51200 + row * 400 + c * 16)         = srch[i];
            *(uint4*)(sm8 + 51200 + 25600 + row * 400 + c * 16) = srcl[i];
        }
    }
    __syncthreads();
    uint32_t Bh[12][4], Bl[12][4];
    {
        const uint32_t bRow = (uint32_t)(nq * 16 + (sel >> 1) * 8 + tt) * 400
                              + (sel & 1) * 16;
        uint32_t bH = sb + 51200 + bRow;
        #pragma unroll
        for (int ks = 0; ks < 12; ks++) {
            ldsm4(Bh[ks], bH + ks * 32);
            ldsm4(Bl[ks], bH + 25600 + ks * 32);
        }
    }

    float2 bias0 = *(const float2*)&bias[chunk * 64 + nq * 16 + qc];
    float2 bias1 = *(const float2*)&bias[chunk * 64 + nq * 16 + 8 + qc];

    const int win0 = grp * PP_W;
    {
        const uint4* sh2 = g_ahi + (size_t)win0 * 1536;
        const uint4* sl2 = g_alo + (size_t)win0 * 1536;
        #pragma unroll
        for (int u = 0; u < 6; u++) {
            int i = tid + u * 256;
            int t = i / 24, c = i - t * 24;
            CP_ASYNC16(sb + t * 400 + c * 16,         (const void*)(sh2 + i));
            CP_ASYNC16(sb + 25600 + t * 400 + c * 16, (const void*)(sl2 + i));
        }
        CP_COMMIT();
    }

    for (int i = 0; i < PP_W; i++) {
        const int win = win0 + i;
        CP_WAIT0();
        __syncthreads();
        if (tid < 64) {
            int wh = (win % 576) / 24, ww = win % 24;
            int sh = wh * 8 + (tid >> 3) + SS_; if (sh >= H_) sh -= H_;
            int sw = ww * 8 + (tid & 7)  + SS_; if (sw >= W_) sw -= W_;
            soff[tid] = sh * W_ + sw;
        }
        if (i + 1 < PP_W) {
            uint32_t nb = sb + (uint32_t)((i + 1) & 1) * 51200;
            const uint4* sh2 = g_ahi + (size_t)(win + 1) * 1536;
            const uint4* sl2 = g_alo + (size_t)(win + 1) * 1536;
            #pragma unroll
            for (int u = 0; u < 6; u++) {
                int ii = tid + u * 256;
                int t = ii / 24, c = ii - t * 24;
                CP_ASYNC16(nb + t * 400 + c * 16,         (const void*)(sh2 + ii));
                CP_ASYNC16(nb + 25600 + t * 400 + c * 16, (const void*)(sl2 + ii));
            }
        }
        CP_COMMIT();

        float acc[2][2][4];
        #pragma unroll
        for (int mt = 0; mt < 2; mt++) {
            acc[mt][0][0] = bias0.x; acc[mt][0][1] = bias0.y;
            acc[mt][0][2] = bias0.x; acc[mt][0][3] = bias0.y;
            acc[mt][1][0] = bias1.x; acc[mt][1][1] = bias1.y;
            acc[mt][1][2] = bias1.x; acc[mt][1][3] = bias1.y;
        }

        const uint32_t abase = sb + (uint32_t)(i & 1) * 51200;
        #pragma unroll
        for (int ks = 0; ks < 12; ks++) {
            #pragma unroll
            for (int mt = 0; mt < 2; mt++) {
                uint32_t ar = abase
                    + (uint32_t)(mh * 32 + mt * 16 + (sel & 1) * 8 + tt) * 400
                    + (sel >> 1) * 16 + ks * 32;
                uint32_t ah[4], al[4];
                ldsm4(ah, ar);
                ldsm4(al, ar + 25600);
                mma16816(acc[mt][0], ah, Bh[ks][0], Bh[ks][1]);
                mma16816(acc[mt][0], al, Bh[ks][0], Bh[ks][1]);
                mma16816(acc[mt][0], ah, Bl[ks][0], Bl[ks][1]);
                mma16816(acc[mt][1], ah, Bh[ks][2], Bh[ks][3]);
                mma16816(acc[mt][1], al, Bh[ks][2], Bh[ks][3]);
                mma16816(acc[mt][1], ah, Bl[ks][2], Bl[ks][3]);
            }
        }

        // res staging for coalesced scatter
        #pragma unroll
        for (int mt = 0; mt < 2; mt++) {
            int t0 = mh * 32 + mt * 16 + qr;
            #pragma unroll
            for (int nt = 0; nt < 2; nt++) {
                int o = nq * 16 + nt * 8 + qc;
                res[o * 66 + t0]           = acc[mt][nt][0];
                res[(o + 1) * 66 + t0]     = acc[mt][nt][1];
                res[o * 66 + t0 + 8]       = acc[mt][nt][2];
                res[(o + 1) * 66 + t0 + 8] = acc[mt][nt][3];
            }
        }
        __syncthreads();

        float* outb = out + (size_t)(win / 576) * C_ * HW_;
        #pragma unroll
        for (int it = 0; it < 16; it++) {
            int idx = tid + it * 256;
            int o = idx >> 6, t = idx & 63;
            outb[(chunk * 64 + o) * HW_ + soff[t]] = res[o * 66 + t];
        }
    }
}

// =====================================================================
extern "C" void kernel_launch(void* const* d_in, const int* in_sizes, int n_in,
                              void* d_out, int out_size) {
    const float* x      = (const float*)d_in[0];
    const float* qkv_w  = (const float*)d_in[1];
    const float* qkv_b  = (const float*)d_in[2];
    const float* proj_w = (const float*)d_in[3];
    const float* proj_b = (const float*)d_in[4];
    const float* tbl    = (const float*)d_in[5];
    float* out = (float*)d_out;

    cudaFuncSetAttribute(k_qkv_pers,  cudaFuncAttributeMaxDynamicSharedMemorySize, 102400);
    cudaFuncSetAttribute(k_attn,      cudaFuncAttributeMaxDynamicSharedMemorySize, 104032);
    cudaFuncSetAttribute(k_proj_pers, cudaFuncAttributeMaxDynamicSharedMemorySize, 119296);

    k_split_w<<<72, 256>>>(qkv_w, proj_w);
    k_split_x<<<NWIN, 256>>>(x);
    k_qkv_pers<<<dim3(QP_NG, 9), 256, 102400>>>(qkv_b);
    k_attn<<<NWIN, 192, 104032>>>(tbl);
    k_proj_pers<<<dim3(PP_NG, 3), 256, 119296>>>(proj_b, out);
}